// round 12
// baseline (speedup 1.0000x reference)
#include <cuda_runtime.h>
#include <math.h>

#define FULLMASK 0xffffffffu
#define CB 2
#define CH 32
#define CHKV 8
#define CR 4
#define CD 128
#define CDIM 4096
#define CSTART 32768
#define CPREF 28672
#define CNPG 1792
#define CPAGE 16
#define CTOP 256
#define CSCALE 0.08838834764831845f

#define SCHUNKS 112  // scoring chunks per (b,hkv): 16 pages each (4 warps x 4)
#define PCH 64       // prefix chunks per (b,hkv): 16 union entries each (4 warps x 4)
#define SCH 32       // suffix chunks per (b,hkv): 128 keys each
#define NPART 512    // per head: 256 prefix warp-partials + 256 suffix
#define PSTR 132     // floats per partial: m, l, pad, pad, acc[128]

// ---------------- scratch (device globals; no allocation allowed) ------------
__device__ float g_q[CB * CH * CD];
__device__ float g_kn[CB * CHKV * CD];
__device__ float g_vn[CB * CHKV * CD];
__device__ float g_sc[CB * CNPG * CHKV * CR];        // [b][page][hkv][r]
__device__ __align__(16) float g_dots[(size_t)CB * CHKV * CR * CPREF];  // [bh][r][key]
__device__ int   g_top[CB * CHKV * CR * CTOP];
__device__ int   g_uni[CB * CHKV * 1024];            // page | mask<<16
__device__ int   g_ucnt[CB * CHKV];
__device__ float g_part[(size_t)CB * CH * NPART * PSTR];
__device__ float g_attn[CB * CDIM];

__device__ __forceinline__ float dot4(float4 a, float4 b) {
    return a.x * b.x + a.y * b.y + a.z * b.z + a.w * b.w;
}

// ---------------- 1) QKV GEMV with fused RoPE --------------------------------
// Warp computes rows (2t, 2t+1) — exactly a RoPE (even,odd) feature pair for
// q/k rows, so RoPE is applied in the epilogue and the rope kernel disappears.
__global__ void qkv_kernel(const float* __restrict__ x, const float* __restrict__ wq,
                           const float* __restrict__ wk, const float* __restrict__ wv,
                           const float* __restrict__ fc, const float* __restrict__ fs) {
    __shared__ float sx0[CDIM], sx1[CDIM];
    for (int i = threadIdx.x; i < CDIM; i += 256) { sx0[i] = x[i]; sx1[i] = x[CDIM + i]; }
    __syncthreads();
    int warp = threadIdx.x >> 5, lane = threadIdx.x & 31;
    int rowA = (blockIdx.x * 8 + warp) * 2;   // 0..6143: [wq 4096 | wk 1024 | wv 1024]
    int rowB = rowA + 1;
    const float* wA = (rowA < 4096) ? wq + (size_t)rowA * CDIM
                     : (rowA < 5120) ? wk + (size_t)(rowA - 4096) * CDIM
                                     : wv + (size_t)(rowA - 5120) * CDIM;
    const float* wB = (rowB < 4096) ? wq + (size_t)rowB * CDIM
                     : (rowB < 5120) ? wk + (size_t)(rowB - 4096) * CDIM
                                     : wv + (size_t)(rowB - 5120) * CDIM;
    float a0 = 0.f, a1 = 0.f, b0 = 0.f, b1 = 0.f;
#pragma unroll 8
    for (int j = lane * 4; j < CDIM; j += 128) {
        float4 va = *(const float4*)(wA + j);
        float4 vb = *(const float4*)(wB + j);
        float4 x0 = *(const float4*)(sx0 + j);
        float4 x1 = *(const float4*)(sx1 + j);
        a0 += dot4(va, x0); a1 += dot4(va, x1);
        b0 += dot4(vb, x0); b1 += dot4(vb, x1);
    }
#pragma unroll
    for (int o = 16; o; o >>= 1) {
        a0 += __shfl_xor_sync(FULLMASK, a0, o);
        a1 += __shfl_xor_sync(FULLMASK, a1, o);
        b0 += __shfl_xor_sync(FULLMASK, b0, o);
        b1 += __shfl_xor_sync(FULLMASK, b1, o);
    }
    if (lane == 0) {
        if (rowA < 5120) {                    // q or k: apply RoPE to the pair
            int feat = (rowA < 4096) ? rowA : (rowA - 4096);
            int i = (feat & 127) >> 1;
            float c = fc[i], s = fs[i];
            float e0 = a0 * c - b0 * s, o0 = a0 * s + b0 * c;   // batch 0
            float e1 = a1 * c - b1 * s, o1 = a1 * s + b1 * c;   // batch 1
            if (rowA < 4096) {
                g_q[rowA] = e0; g_q[rowB] = o0;
                g_q[CDIM + rowA] = e1; g_q[CDIM + rowB] = o1;
            } else {
                int ia = rowA - 4096, ib = rowB - 4096;
                g_kn[ia] = e0; g_kn[ib] = o0;
                g_kn[CHKV * CD + ia] = e1; g_kn[CHKV * CD + ib] = o1;
            }
        } else {
            int ia = rowA - 5120, ib = rowB - 5120;
            g_vn[ia] = a0; g_vn[ib] = b0;
            g_vn[CHKV * CD + ia] = a1; g_vn[CHKV * CD + ib] = b1;
        }
    }
}

// ---------------- 3) page scoring + dot caching (contiguous-split loads) -----
// Lane sub loads row[sub*4..+4) and row[64+sub*4..+4): each LDG's 16 lanes
// cover 256 contiguous bytes = 2 L1 lines (was 4 at stride-32), halving
// L1 wavefront pressure at identical DRAM traffic.
__global__ void __launch_bounds__(128, 12) score_kernel(const float* __restrict__ ck) {
    int bid = blockIdx.x;
    int chunk = bid % SCHUNKS;
    int bh = bid / SCHUNKS;
    int hkv = bh % CHKV, b = bh / CHKV;
    int warp = threadIdx.x >> 5, lane = threadIdx.x & 31;
    int half = lane >> 4, sub = lane & 15;
    bool p = lane & 1;
    const float* qb = g_q + (b * CH + hkv * CR + 2 * half) * CD;
    float4 q0a = *(const float4*)(qb + sub * 4);
    float4 q0b = *(const float4*)(qb + 64 + sub * 4);
    float4 q1a = *(const float4*)(qb + CD + sub * 4);
    float4 q1b = *(const float4*)(qb + CD + 64 + sub * 4);
    int page0 = chunk * 16 + warp * 4;
    int r = 2 * half + (int)p;
    float* drow = g_dots + ((size_t)bh * CR + r) * CPREF;
    for (int pp = 0; pp < 4; pp++) {
        int page = page0 + pp;
        const float* kp = ck + (((size_t)b * CSTART + (size_t)page * CPAGE) * CHKV + hkv) * CD;
        float mx = -1e30f;
#pragma unroll
        for (int g = 0; g < 2; g++) {
            float s[8];
#pragma unroll
            for (int k = 0; k < 8; k++) {
                const float* row = kp + (size_t)(g * 8 + k) * (CHKV * CD);
                float4 ka = *(const float4*)(row + sub * 4);
                float4 kb = *(const float4*)(row + 64 + sub * 4);
                float v0 = dot4(ka, q0a) + dot4(kb, q0b);
                float v1 = dot4(ka, q1a) + dot4(kb, q1b);
                float a = p ? v1 : v0, bb2 = p ? v0 : v1;
                s[k] = a + __shfl_xor_sync(FULLMASK, bb2, 1);
            }
#pragma unroll
            for (int k = 0; k < 8; k++) {
                float a = s[k];
                a += __shfl_xor_sync(FULLMASK, a, 2);
                a += __shfl_xor_sync(FULLMASK, a, 4);
                a += __shfl_xor_sync(FULLMASK, a, 8);
                s[k] = a;
            }
            if ((lane & 14) == 0) {    // lanes 0,1,16,17
                *(float4*)(drow + page * CPAGE + g * 8)     = make_float4(s[0], s[1], s[2], s[3]);
                *(float4*)(drow + page * CPAGE + g * 8 + 4) = make_float4(s[4], s[5], s[6], s[7]);
            }
#pragma unroll
            for (int k = 0; k < 8; k++) mx = fmaxf(mx, s[k]);
        }
        if ((lane & 14) == 0)
            g_sc[((b * CNPG + page) * CHKV + hkv) * CR + r] = mx;
    }
}

// ---------------- 4) top-256 SET per (b,hkv,r): radix histogram select -------
__global__ void __launch_bounds__(256) topk_kernel() {
    __shared__ int hist[256];
    __shared__ int scan[256];
    __shared__ unsigned s_prefix;
    __shared__ int s_need, s_cnt, s_eqn;
    __shared__ int eq[2048];
    int inst = blockIdx.x;                    // b*32 + hkv*4 + r
    int r = inst & 3, hkv = (inst >> 2) & 7, b = inst >> 5;
    int t = threadIdx.x;
    unsigned su[7];
#pragma unroll
    for (int j = 0; j < 7; j++) {
        int i = t + j * 256;                  // 7*256 = 1792 = CNPG
        float f = g_sc[((b * CNPG + i) * CHKV + hkv) * CR + r];
        unsigned u = __float_as_uint(f);
        su[j] = (u >> 31) ? ~u : (u | 0x80000000u);   // larger float = larger su
    }
    if (t == 0) { s_prefix = 0; s_need = CTOP; }
    for (int level = 0; level < 4; level++) {
        int shift = 24 - level * 8;
        hist[t] = 0;
        __syncthreads();
        unsigned pfx = s_prefix;
        unsigned maskAbove = (level == 0) ? 0u : (0xFFFFFFFFu << (shift + 8));
#pragma unroll
        for (int j = 0; j < 7; j++)
            if ((su[j] & maskAbove) == pfx)
                atomicAdd(&hist[(su[j] >> shift) & 255], 1);
        __syncthreads();
        scan[t] = hist[t];                    // inclusive suffix-sum
        for (int o = 1; o < 256; o <<= 1) {
            __syncthreads();
            int v = (t + o < 256) ? scan[t + o] : 0;
            __syncthreads();
            scan[t] += v;
        }
        __syncthreads();
        int need = s_need;
        __syncthreads();
        if (scan[t] >= need && (t == 255 || scan[t + 1] < need)) {
            s_prefix = pfx | ((unsigned)t << shift);
            s_need = need - ((t == 255) ? 0 : scan[t + 1]);
        }
        __syncthreads();
    }
    unsigned V = s_prefix;
    int needEq = s_need;
    if (t == 0) { s_cnt = 0; s_eqn = 0; }
    __syncthreads();
#pragma unroll
    for (int j = 0; j < 7; j++) {
        int i = t + j * 256;
        if (su[j] > V) {
            int slot = atomicAdd(&s_cnt, 1);
            g_top[inst * CTOP + slot] = i;
        } else if (su[j] == V) {
            int e = atomicAdd(&s_eqn, 1);
            eq[e] = i;
        }
    }
    __syncthreads();
    int base = s_cnt;                         // == 256 - needEq
    int eqn = s_eqn;
    if (needEq > 0) {
        if (needEq < eqn && eqn > 1) {        // sort equals ascending, take first needEq
            int P = 1; while (P < eqn) P <<= 1;
            for (int i = t + eqn; i < P; i += 256) eq[i] = 0x7FFFFFFF;
            __syncthreads();
            for (int k = 2; k <= P; k <<= 1)
                for (int jj = k >> 1; jj; jj >>= 1) {
                    for (int s = t; s < P / 2; s += 256) {
                        int i = ((s & ~(jj - 1)) << 1) | (s & (jj - 1));
                        int ixj = i | jj;
                        int A = eq[i], Bv = eq[ixj];
                        bool desc = (i & k) != 0;
                        if ((A > Bv) != desc) { eq[i] = Bv; eq[ixj] = A; }
                    }
                    __syncthreads();
                }
        }
        __syncthreads();
        for (int i = t; i < needEq; i += 256)
            g_top[inst * CTOP + base + i] = eq[i];
    }
}

// ---------------- 5) union of pages across 4 reps + mask, deterministic -----
__global__ void union_kernel() {
    __shared__ int mask[CNPG];
    __shared__ int wtot[8];
    int bh = blockIdx.x;
    int warp = threadIdx.x >> 5, lane = threadIdx.x & 31;
    for (int i = threadIdx.x; i < CNPG; i += 256) mask[i] = 0;
    __syncthreads();
    for (int r = 0; r < CR; r++) {
        int i = threadIdx.x;
        if (i < CTOP) {
            int p = g_top[(bh * CR + r) * CTOP + i];
            atomicOr(&mask[p], 1 << r);
        }
    }
    __syncthreads();
    int base = threadIdx.x * 7;
    int cnt = 0;
    for (int j = 0; j < 7; j++) if (mask[base + j]) cnt++;
    int v = cnt;
    for (int o = 1; o < 32; o <<= 1) {
        int u = __shfl_up_sync(FULLMASK, v, o);
        if (lane >= o) v += u;
    }
    if (lane == 31) wtot[warp] = v;
    __syncthreads();
    if (threadIdx.x == 0) {
        int s = 0;
        for (int i = 0; i < 8; i++) { int t = wtot[i]; wtot[i] = s; s += t; }
        g_ucnt[bh] = (s > 1024) ? 1024 : s;
    }
    __syncthreads();
    int off = v - cnt + wtot[warp];
    for (int j = 0; j < 7; j++) {
        int p = base + j;
        int mk = mask[p];
        if (mk && off < 1024) g_uni[bh * 1024 + off++] = p | (mk << 16);
    }
}

// ---------------- write one r-state partial (contiguous-split layout) -------
// aa covers dims [sub*4, sub*4+4), ab covers [64+sub*4, 64+sub*4+4).
__device__ __forceinline__ void wpart2(float m, float l, float4 aa, float4 ab,
                                       int b, int hr, int slot, int sub) {
    float* P = g_part + (((size_t)(b * CH + hr)) * NPART + slot) * PSTR;
    if (sub == 0) { P[0] = m; P[1] = l; }
    *(float4*)(P + 4 + sub * 4)      = aa;
    *(float4*)(P + 4 + 64 + sub * 4) = ab;
}

// ---------------- 6) prefix attention: dots-fed, V-only ----------------------
__global__ void __launch_bounds__(128, 10) prefix_kernel(const float* __restrict__ cv) {
    int bid = blockIdx.x;
    int chunk = bid % PCH;
    int bh = bid / PCH;
    int hkv = bh % CHKV, b = bh / CHKV;
    int warp = threadIdx.x >> 5, lane = threadIdx.x & 31;
    int half = lane >> 4, sub = lane & 15;
    int cnt = g_ucnt[bh];
    float m0 = -1e30f, l0 = 0.f, m1 = -1e30f, l1 = 0.f;
    float4 a0a = make_float4(0, 0, 0, 0), a0b = a0a, a1a = a0a, a1b = a0a;
    const float* dr0 = g_dots + ((size_t)bh * CR + 2 * half) * CPREF;
    const float* dr1 = dr0 + CPREF;
    int e0i = chunk * 16 + warp * 4;
    for (int ei = e0i; ei < e0i + 4 && ei < cnt; ei++) {
        int ent = g_uni[bh * 1024 + ei];
        int page = ent & 0xFFFF;
        int pm = ent >> 16;
        bool en0 = (pm >> (2 * half)) & 1;
        bool en1 = (pm >> (2 * half + 1)) & 1;
        const float* vp = cv + (((size_t)b * CSTART + (size_t)page * CPAGE) * CHKV + hkv) * CD;
#pragma unroll
        for (int g = 0; g < 2; g++) {
            float4 dA0 = *(const float4*)(dr0 + page * CPAGE + g * 8);
            float4 dA1 = *(const float4*)(dr0 + page * CPAGE + g * 8 + 4);
            float4 dB0 = *(const float4*)(dr1 + page * CPAGE + g * 8);
            float4 dB1 = *(const float4*)(dr1 + page * CPAGE + g * 8 + 4);
            float sA[8] = { dA0.x, dA0.y, dA0.z, dA0.w, dA1.x, dA1.y, dA1.z, dA1.w };
            float sB[8] = { dB0.x, dB0.y, dB0.z, dB0.w, dB1.x, dB1.y, dB1.z, dB1.w };
            float eA[8], eB[8];
            if (en0) {
                float tm = sA[0];
#pragma unroll
                for (int k = 1; k < 8; k++) tm = fmaxf(tm, sA[k]);
                float nm = fmaxf(m0, tm * CSCALE);
                float cr = __expf(m0 - nm);
                float se = 0.f;
#pragma unroll
                for (int k = 0; k < 8; k++) { eA[k] = __expf(sA[k] * CSCALE - nm); se += eA[k]; }
                l0 = l0 * cr + se; m0 = nm;
                a0a.x *= cr; a0a.y *= cr; a0a.z *= cr; a0a.w *= cr;
                a0b.x *= cr; a0b.y *= cr; a0b.z *= cr; a0b.w *= cr;
            }
            if (en1) {
                float tm = sB[0];
#pragma unroll
                for (int k = 1; k < 8; k++) tm = fmaxf(tm, sB[k]);
                float nm = fmaxf(m1, tm * CSCALE);
                float cr = __expf(m1 - nm);
                float se = 0.f;
#pragma unroll
                for (int k = 0; k < 8; k++) { eB[k] = __expf(sB[k] * CSCALE - nm); se += eB[k]; }
                l1 = l1 * cr + se; m1 = nm;
                a1a.x *= cr; a1a.y *= cr; a1a.z *= cr; a1a.w *= cr;
                a1b.x *= cr; a1b.y *= cr; a1b.z *= cr; a1b.w *= cr;
            }
#pragma unroll
            for (int k = 0; k < 8; k++) {
                const float* row = vp + (size_t)(g * 8 + k) * (CHKV * CD);
                float4 va = *(const float4*)(row + sub * 4);
                float4 vb = *(const float4*)(row + 64 + sub * 4);
                if (en0) {
                    float e = eA[k];
                    a0a.x += e * va.x; a0a.y += e * va.y; a0a.z += e * va.z; a0a.w += e * va.w;
                    a0b.x += e * vb.x; a0b.y += e * vb.y; a0b.z += e * vb.z; a0b.w += e * vb.w;
                }
                if (en1) {
                    float e = eB[k];
                    a1a.x += e * va.x; a1a.y += e * va.y; a1a.z += e * va.z; a1a.w += e * va.w;
                    a1b.x += e * vb.x; a1b.y += e * vb.y; a1b.z += e * vb.z; a1b.w += e * vb.w;
                }
            }
        }
    }
    int slot = chunk * 4 + warp;              // 0..255
    int hr = hkv * CR + 2 * half;
    wpart2(m0, l0, a0a, a0b, b, hr, slot, sub);
    wpart2(m1, l1, a1a, a1b, b, hr + 1, slot, sub);
}

// ---------------- suffix helpers (per-key flash, half-warp r-pair) -----------
#define UPD2(MM, LL, ACA, ACB, SV)                                                   \
    do {                                                                             \
        if ((SV) > (MM)) {                                                           \
            float cr_ = __expf((MM) - (SV));                                         \
            MM = (SV); LL *= cr_;                                                    \
            ACA.x *= cr_; ACA.y *= cr_; ACA.z *= cr_; ACA.w *= cr_;                  \
            ACB.x *= cr_; ACB.y *= cr_; ACB.z *= cr_; ACB.w *= cr_;                  \
        }                                                                            \
        float e_ = __expf((SV) - (MM));                                              \
        LL += e_;                                                                    \
        ACA.x += e_ * va.x; ACA.y += e_ * va.y; ACA.z += e_ * va.z; ACA.w += e_ * va.w; \
        ACB.x += e_ * vb.x; ACB.y += e_ * vb.y; ACB.z += e_ * vb.z; ACB.w += e_ * vb.w; \
    } while (0)

struct HState {
    float m0, l0, m1, l1;
    float4 a0a, a0b, a1a, a1b;
};

__device__ __forceinline__ void key_step2(HState& st, float4 ka, float4 kb,
                                          float4 va, float4 vb,
                                          float4 q0a, float4 q0b, float4 q1a, float4 q1b,
                                          bool p) {
    float v0 = dot4(ka, q0a) + dot4(kb, q0b);
    float v1 = dot4(ka, q1a) + dot4(kb, q1b);
    float a = p ? v1 : v0, bb = p ? v0 : v1;
    a += __shfl_xor_sync(FULLMASK, bb, 1);
    a += __shfl_xor_sync(FULLMASK, a, 2);
    a += __shfl_xor_sync(FULLMASK, a, 4);
    a += __shfl_xor_sync(FULLMASK, a, 8);
    a *= CSCALE;
    float so = __shfl_xor_sync(FULLMASK, a, 1);
    float sA = p ? so : a;
    float sB = p ? a : so;
    UPD2(st.m0, st.l0, st.a0a, st.a0b, sA);
    UPD2(st.m1, st.l1, st.a1a, st.a1b, sB);
}

// ---------------- 7) suffix attention (window 4096 + new token) --------------
__global__ void suffix_kernel(const float* __restrict__ ck, const float* __restrict__ cv) {
    int bid = blockIdx.x;
    int chunk = bid % SCH;
    int bh = bid / SCH;
    int hkv = bh % CHKV, b = bh / CHKV;
    int warp = threadIdx.x >> 5, lane = threadIdx.x & 31;
    int half = lane >> 4, sub = lane & 15;
    bool p = lane & 1;
    const float* qb = g_q + (b * CH + hkv * CR + 2 * half) * CD;
    float4 q0a = *(const float4*)(qb + sub * 4);
    float4 q0b = *(const float4*)(qb + 64 + sub * 4);
    float4 q1a = *(const float4*)(qb + CD + sub * 4);
    float4 q1b = *(const float4*)(qb + CD + 64 + sub * 4);
    HState st;
    st.m0 = st.m1 = -1e30f;
    st.l0 = st.l1 = 0.f;
    st.a0a = st.a0b = st.a1a = st.a1b = make_float4(0.f, 0.f, 0.f, 0.f);
    int key0 = chunk * 128 + warp * 16;
    size_t boff = (((size_t)b * CSTART + CPREF + key0) * CHKV + hkv) * CD;
    const float* kp = ck + boff;
    const float* vp = cv + boff;
    for (int g = 0; g < 8; g++) {
        const float* kr0 = kp + (size_t)(2 * g) * (CHKV * CD);
        const float* vr0 = vp + (size_t)(2 * g) * (CHKV * CD);
        const float* kr1 = kp + (size_t)(2 * g + 1) * (CHKV * CD);
        const float* vr1 = vp + (size_t)(2 * g + 1) * (CHKV * CD);
        float4 ka0 = *(const float4*)(kr0 + sub * 4), kb0 = *(const float4*)(kr0 + 64 + sub * 4);
        float4 va0 = *(const float4*)(vr0 + sub * 4), vb0 = *(const float4*)(vr0 + 64 + sub * 4);
        float4 ka1 = *(const float4*)(kr1 + sub * 4), kb1 = *(const float4*)(kr1 + 64 + sub * 4);
        float4 va1 = *(const float4*)(vr1 + sub * 4), vb1 = *(const float4*)(vr1 + 64 + sub * 4);
        key_step2(st, ka0, kb0, va0, vb0, q0a, q0b, q1a, q1b, p);
        key_step2(st, ka1, kb1, va1, vb1, q0a, q0b, q1a, q1b, p);
    }
    if (chunk == SCH - 1 && warp == 7) {       // the just-computed token
        const float* knp = g_kn + (b * CHKV + hkv) * CD;
        const float* vnp = g_vn + (b * CHKV + hkv) * CD;
        float4 ka = *(const float4*)(knp + sub * 4), kb = *(const float4*)(knp + 64 + sub * 4);
        float4 va = *(const float4*)(vnp + sub * 4), vb = *(const float4*)(vnp + 64 + sub * 4);
        key_step2(st, ka, kb, va, vb, q0a, q0b, q1a, q1b, p);
    }
    int slot = 256 + chunk * 8 + warp;
    int hr = hkv * CR + 2 * half;
    wpart2(st.m0, st.l0, st.a0a, st.a0b, b, hr, slot, sub);
    wpart2(st.m1, st.l1, st.a1a, st.a1b, b, hr + 1, slot, sub);
}

// ---------------- 8) merge all partials (exact logaddexp combine) ------------
__global__ void combine_kernel() {
    int bh = blockIdx.x;                       // b*H + h
    const float* P = g_part + (size_t)bh * NPART * PSTR;
    __shared__ float red[128];
    __shared__ float coef[NPART];
    int t = threadIdx.x;
    float mloc = -1e30f;
    for (int c = t; c < NPART; c += 128) mloc = fmaxf(mloc, P[(size_t)c * PSTR]);
    red[t] = mloc;
    for (int o = 64; o; o >>= 1) { __syncthreads(); if (t < o) red[t] = fmaxf(red[t], red[t + o]); }
    __syncthreads();
    float M = red[0];
    __syncthreads();
    float lloc = 0.f;
    for (int c = t; c < NPART; c += 128) {
        float w = __expf(P[(size_t)c * PSTR] - M);
        coef[c] = w;
        lloc += w * P[(size_t)c * PSTR + 1];
    }
    red[t] = lloc;
    for (int o = 64; o; o >>= 1) { __syncthreads(); if (t < o) red[t] += red[t + o]; }
    __syncthreads();
    float L = red[0];
    float o = 0.f;
    for (int c = 0; c < NPART; c++) o += coef[c] * P[(size_t)c * PSTR + 4 + t];
    int b = bh >> 5, h = bh & 31;
    g_attn[b * CDIM + h * CD + t] = o / L;
}

// ---------------- 9) output GEMV: 2 rows interleaved -------------------------
__global__ void out_kernel(const float* __restrict__ wo, float* __restrict__ out) {
    __shared__ float sa0[CDIM], sa1[CDIM];
    for (int i = threadIdx.x; i < CDIM; i += 256) { sa0[i] = g_attn[i]; sa1[i] = g_attn[CDIM + i]; }
    __syncthreads();
    int warp = threadIdx.x >> 5, lane = threadIdx.x & 31;
    int rowA = (blockIdx.x * 8 + warp) * 2;   // 256 blocks cover 4096 rows
    int rowB = rowA + 1;
    const float* wA = wo + (size_t)rowA * CDIM;
    const float* wB = wo + (size_t)rowB * CDIM;
    float a0 = 0.f, a1 = 0.f, b0 = 0.f, b1 = 0.f;
#pragma unroll 8
    for (int j = lane * 4; j < CDIM; j += 128) {
        float4 va = *(const float4*)(wA + j);
        float4 vb = *(const float4*)(wB + j);
        float4 x0 = *(const float4*)(sa0 + j);
        float4 x1 = *(const float4*)(sa1 + j);
        a0 += dot4(va, x0); a1 += dot4(va, x1);
        b0 += dot4(vb, x0); b1 += dot4(vb, x1);
    }
#pragma unroll
    for (int o = 16; o; o >>= 1) {
        a0 += __shfl_xor_sync(FULLMASK, a0, o);
        a1 += __shfl_xor_sync(FULLMASK, a1, o);
        b0 += __shfl_xor_sync(FULLMASK, b0, o);
        b1 += __shfl_xor_sync(FULLMASK, b1, o);
    }
    if (lane == 0) {
        out[rowA] = a0; out[CDIM + rowA] = a1;
        out[rowB] = b0; out[CDIM + rowB] = b1;
    }
}

// ---------------- streams/events for fork-join (created once, host-side) -----
struct SideStream {
    cudaStream_t s2;
    cudaEvent_t e_fork, e_join;
    SideStream() {
        cudaStreamCreateWithFlags(&s2, cudaStreamNonBlocking);
        cudaEventCreateWithFlags(&e_fork, cudaEventDisableTiming);
        cudaEventCreateWithFlags(&e_join, cudaEventDisableTiming);
    }
};
static SideStream g_ss;

// ---------------- launch ------------------------------------------------------
extern "C" void kernel_launch(void* const* d_in, const int* in_sizes, int n_in,
                              void* d_out, int out_size) {
    (void)in_sizes; (void)n_in; (void)out_size;
    const float* x    = (const float*)d_in[0];
    const float* fcos = (const float*)d_in[1];
    const float* fsin = (const float*)d_in[2];
    const float* ck   = (const float*)d_in[3];
    const float* cv   = (const float*)d_in[4];
    const float* wq   = (const float*)d_in[5];
    const float* wk   = (const float*)d_in[6];
    const float* wv   = (const float*)d_in[7];
    const float* wo   = (const float*)d_in[8];
    float* out = (float*)d_out;

    qkv_kernel<<<384, 256>>>(x, wq, wk, wv, fcos, fsin);

    // fork: suffix depends only on q/kn/vn (RoPE fused into qkv)
    cudaEventRecord(g_ss.e_fork, 0);
    cudaStreamWaitEvent(g_ss.s2, g_ss.e_fork, 0);
    suffix_kernel<<<CB * CHKV * SCH, 256, 0, g_ss.s2>>>(ck, cv);
    cudaEventRecord(g_ss.e_join, g_ss.s2);

    score_kernel<<<CB * CHKV * SCHUNKS, 128>>>(ck);
    topk_kernel<<<CB * CHKV * CR, 256>>>();
    union_kernel<<<CB * CHKV, 256>>>();
    prefix_kernel<<<CB * CHKV * PCH, 128>>>(cv);

    // join before combine
    cudaStreamWaitEvent(0, g_ss.e_join, 0);
    combine_kernel<<<CB * CH, 128>>>();
    out_kernel<<<256, 256>>>(wo, out);
}

// round 13
// speedup vs baseline: 1.0116x; 1.0116x over previous
#include <cuda_runtime.h>
#include <math.h>

#define FULLMASK 0xffffffffu
#define CB 2
#define CH 32
#define CHKV 8
#define CR 4
#define CD 128
#define CDIM 4096
#define CSTART 32768
#define CPREF 28672
#define CNPG 1792
#define CPAGE 16
#define CTOP 256
#define CSCALE 0.08838834764831845f

#define SCHUNKS 112  // scoring chunks per (b,hkv): 16 pages each (4 warps x 4)
#define PCH 64       // prefix chunks per (b,hkv): 16 union entries each (4 warps x 4)
#define SCH 32       // suffix chunks per (b,hkv): 128 keys each
#define NPART 512    // per head: 256 prefix warp-partials + 256 suffix
#define PSTR 132     // floats per partial: m, l, pad, pad, acc[128]

// ---------------- scratch (device globals; no allocation allowed) ------------
__device__ float g_q[CB * CH * CD];
__device__ float g_kn[CB * CHKV * CD];
__device__ float g_vn[CB * CHKV * CD];
__device__ float g_sc[CB * CNPG * CHKV * CR];        // [b][page][hkv][r]
__device__ __align__(16) float g_dots[(size_t)CB * CHKV * CR * CPREF];  // [bh][r][key]
__device__ int   g_top[CB * CHKV * CR * CTOP];
__device__ int   g_uni[CB * CHKV * 1024];            // page | mask<<16
__device__ int   g_ucnt[CB * CHKV];
__device__ float g_part[(size_t)CB * CH * NPART * PSTR];
__device__ float g_attn[CB * CDIM];

__device__ __forceinline__ float dot4(float4 a, float4 b) {
    return a.x * b.x + a.y * b.y + a.z * b.z + a.w * b.w;
}

// ---------------- 1a) Q GEMV with fused RoPE (rows 0..4095) ------------------
__global__ void qkv_q_kernel(const float* __restrict__ x, const float* __restrict__ wq,
                             const float* __restrict__ fc, const float* __restrict__ fs) {
    __shared__ float sx0[CDIM], sx1[CDIM];
    for (int i = threadIdx.x; i < CDIM; i += 256) { sx0[i] = x[i]; sx1[i] = x[CDIM + i]; }
    __syncthreads();
    int warp = threadIdx.x >> 5, lane = threadIdx.x & 31;
    int rowA = (blockIdx.x * 8 + warp) * 2;   // 0..4094 even
    int rowB = rowA + 1;
    const float* wA = wq + (size_t)rowA * CDIM;
    const float* wB = wq + (size_t)rowB * CDIM;
    float a0 = 0.f, a1 = 0.f, b0 = 0.f, b1 = 0.f;
#pragma unroll 8
    for (int j = lane * 4; j < CDIM; j += 128) {
        float4 va = *(const float4*)(wA + j);
        float4 vb = *(const float4*)(wB + j);
        float4 x0 = *(const float4*)(sx0 + j);
        float4 x1 = *(const float4*)(sx1 + j);
        a0 += dot4(va, x0); a1 += dot4(va, x1);
        b0 += dot4(vb, x0); b1 += dot4(vb, x1);
    }
#pragma unroll
    for (int o = 16; o; o >>= 1) {
        a0 += __shfl_xor_sync(FULLMASK, a0, o);
        a1 += __shfl_xor_sync(FULLMASK, a1, o);
        b0 += __shfl_xor_sync(FULLMASK, b0, o);
        b1 += __shfl_xor_sync(FULLMASK, b1, o);
    }
    if (lane == 0) {
        int i = (rowA & 127) >> 1;
        float c = fc[i], s = fs[i];
        g_q[rowA] = a0 * c - b0 * s;  g_q[rowB] = a0 * s + b0 * c;
        g_q[CDIM + rowA] = a1 * c - b1 * s;  g_q[CDIM + rowB] = a1 * s + b1 * c;
    }
}

// ---------------- 1b) KV GEMV with fused RoPE on K (rows 4096..6143) ---------
__global__ void qkv_kv_kernel(const float* __restrict__ x, const float* __restrict__ wk,
                              const float* __restrict__ wv,
                              const float* __restrict__ fc, const float* __restrict__ fs) {
    __shared__ float sx0[CDIM], sx1[CDIM];
    for (int i = threadIdx.x; i < CDIM; i += 256) { sx0[i] = x[i]; sx1[i] = x[CDIM + i]; }
    __syncthreads();
    int warp = threadIdx.x >> 5, lane = threadIdx.x & 31;
    int rowA = 4096 + (blockIdx.x * 8 + warp) * 2;   // 4096..6142 even
    int rowB = rowA + 1;
    const float* wA = (rowA < 5120) ? wk + (size_t)(rowA - 4096) * CDIM
                                    : wv + (size_t)(rowA - 5120) * CDIM;
    const float* wB = (rowB < 5120) ? wk + (size_t)(rowB - 4096) * CDIM
                                    : wv + (size_t)(rowB - 5120) * CDIM;
    float a0 = 0.f, a1 = 0.f, b0 = 0.f, b1 = 0.f;
#pragma unroll 8
    for (int j = lane * 4; j < CDIM; j += 128) {
        float4 va = *(const float4*)(wA + j);
        float4 vb = *(const float4*)(wB + j);
        float4 x0 = *(const float4*)(sx0 + j);
        float4 x1 = *(const float4*)(sx1 + j);
        a0 += dot4(va, x0); a1 += dot4(va, x1);
        b0 += dot4(vb, x0); b1 += dot4(vb, x1);
    }
#pragma unroll
    for (int o = 16; o; o >>= 1) {
        a0 += __shfl_xor_sync(FULLMASK, a0, o);
        a1 += __shfl_xor_sync(FULLMASK, a1, o);
        b0 += __shfl_xor_sync(FULLMASK, b0, o);
        b1 += __shfl_xor_sync(FULLMASK, b1, o);
    }
    if (lane == 0) {
        if (rowA < 5120) {                    // k rows: RoPE the pair
            int feat = rowA - 4096;
            int i = (feat & 127) >> 1;
            float c = fc[i], s = fs[i];
            int ia = rowA - 4096, ib = rowB - 4096;
            g_kn[ia] = a0 * c - b0 * s;  g_kn[ib] = a0 * s + b0 * c;
            g_kn[CHKV * CD + ia] = a1 * c - b1 * s;  g_kn[CHKV * CD + ib] = a1 * s + b1 * c;
        } else {
            int ia = rowA - 5120, ib = rowB - 5120;
            g_vn[ia] = a0; g_vn[ib] = b0;
            g_vn[CHKV * CD + ia] = a1; g_vn[CHKV * CD + ib] = b1;
        }
    }
}

// ---------------- 3) page scoring + dot caching (contiguous-split loads) -----
__global__ void __launch_bounds__(128, 12) score_kernel(const float* __restrict__ ck) {
    int bid = blockIdx.x;
    int chunk = bid % SCHUNKS;
    int bh = bid / SCHUNKS;
    int hkv = bh % CHKV, b = bh / CHKV;
    int warp = threadIdx.x >> 5, lane = threadIdx.x & 31;
    int half = lane >> 4, sub = lane & 15;
    bool p = lane & 1;
    const float* qb = g_q + (b * CH + hkv * CR + 2 * half) * CD;
    float4 q0a = *(const float4*)(qb + sub * 4);
    float4 q0b = *(const float4*)(qb + 64 + sub * 4);
    float4 q1a = *(const float4*)(qb + CD + sub * 4);
    float4 q1b = *(const float4*)(qb + CD + 64 + sub * 4);
    int page0 = chunk * 16 + warp * 4;
    int r = 2 * half + (int)p;
    float* drow = g_dots + ((size_t)bh * CR + r) * CPREF;
    for (int pp = 0; pp < 4; pp++) {
        int page = page0 + pp;
        const float* kp = ck + (((size_t)b * CSTART + (size_t)page * CPAGE) * CHKV + hkv) * CD;
        float mx = -1e30f;
#pragma unroll
        for (int g = 0; g < 2; g++) {
            float s[8];
#pragma unroll
            for (int k = 0; k < 8; k++) {
                const float* row = kp + (size_t)(g * 8 + k) * (CHKV * CD);
                float4 ka = *(const float4*)(row + sub * 4);
                float4 kb = *(const float4*)(row + 64 + sub * 4);
                float v0 = dot4(ka, q0a) + dot4(kb, q0b);
                float v1 = dot4(ka, q1a) + dot4(kb, q1b);
                float a = p ? v1 : v0, bb2 = p ? v0 : v1;
                s[k] = a + __shfl_xor_sync(FULLMASK, bb2, 1);
            }
#pragma unroll
            for (int k = 0; k < 8; k++) {
                float a = s[k];
                a += __shfl_xor_sync(FULLMASK, a, 2);
                a += __shfl_xor_sync(FULLMASK, a, 4);
                a += __shfl_xor_sync(FULLMASK, a, 8);
                s[k] = a;
            }
            if ((lane & 14) == 0) {    // lanes 0,1,16,17
                *(float4*)(drow + page * CPAGE + g * 8)     = make_float4(s[0], s[1], s[2], s[3]);
                *(float4*)(drow + page * CPAGE + g * 8 + 4) = make_float4(s[4], s[5], s[6], s[7]);
            }
#pragma unroll
            for (int k = 0; k < 8; k++) mx = fmaxf(mx, s[k]);
        }
        if ((lane & 14) == 0)
            g_sc[((b * CNPG + page) * CHKV + hkv) * CR + r] = mx;
    }
}

// ---------------- 4) top-256 SET: radix select with warp-shuffle scan --------
__global__ void __launch_bounds__(256) topk_kernel() {
    __shared__ int hist[256];
    __shared__ int scan[256];
    __shared__ int wsum[8];
    __shared__ unsigned s_prefix;
    __shared__ int s_need, s_cnt, s_eqn;
    __shared__ int eq[2048];
    int inst = blockIdx.x;                    // b*32 + hkv*4 + r
    int r = inst & 3, hkv = (inst >> 2) & 7, b = inst >> 5;
    int t = threadIdx.x;
    int lane = t & 31, w = t >> 5;
    unsigned su[7];
#pragma unroll
    for (int j = 0; j < 7; j++) {
        int i = t + j * 256;                  // 7*256 = 1792 = CNPG
        float f = g_sc[((b * CNPG + i) * CHKV + hkv) * CR + r];
        unsigned u = __float_as_uint(f);
        su[j] = (u >> 31) ? ~u : (u | 0x80000000u);   // larger float = larger su
    }
    if (t == 0) { s_prefix = 0; s_need = CTOP; }
    for (int level = 0; level < 4; level++) {
        int shift = 24 - level * 8;
        hist[t] = 0;
        __syncthreads();
        unsigned pfx = s_prefix;
        unsigned maskAbove = (level == 0) ? 0u : (0xFFFFFFFFu << (shift + 8));
#pragma unroll
        for (int j = 0; j < 7; j++)
            if ((su[j] & maskAbove) == pfx)
                atomicAdd(&hist[(su[j] >> shift) & 255], 1);
        __syncthreads();
        // inclusive suffix-sum via warp shuffles (2 barriers total)
        int v = hist[t];
#pragma unroll
        for (int o = 1; o < 32; o <<= 1) {
            int u2 = __shfl_down_sync(FULLMASK, v, o);
            if (lane + o < 32) v += u2;
        }
        if (lane == 0) wsum[w] = v;           // warp total (suffix at lane 0)
        __syncthreads();
        int add = 0;
#pragma unroll
        for (int w2 = 0; w2 < 8; w2++) if (w2 > w) add += wsum[w2];
        scan[t] = v + add;
        __syncthreads();
        int need = s_need;
        __syncthreads();
        if (scan[t] >= need && (t == 255 || scan[t + 1] < need)) {
            s_prefix = pfx | ((unsigned)t << shift);
            s_need = need - ((t == 255) ? 0 : scan[t + 1]);
        }
        __syncthreads();
    }
    unsigned V = s_prefix;
    int needEq = s_need;
    if (t == 0) { s_cnt = 0; s_eqn = 0; }
    __syncthreads();
#pragma unroll
    for (int j = 0; j < 7; j++) {
        int i = t + j * 256;
        if (su[j] > V) {
            int slot = atomicAdd(&s_cnt, 1);
            g_top[inst * CTOP + slot] = i;
        } else if (su[j] == V) {
            int e = atomicAdd(&s_eqn, 1);
            eq[e] = i;
        }
    }
    __syncthreads();
    int base = s_cnt;                         // == 256 - needEq
    int eqn = s_eqn;
    if (needEq > 0) {
        if (needEq < eqn && eqn > 1) {        // sort equals ascending, take first needEq
            int P = 1; while (P < eqn) P <<= 1;
            for (int i = t + eqn; i < P; i += 256) eq[i] = 0x7FFFFFFF;
            __syncthreads();
            for (int k = 2; k <= P; k <<= 1)
                for (int jj = k >> 1; jj; jj >>= 1) {
                    for (int s = t; s < P / 2; s += 256) {
                        int i = ((s & ~(jj - 1)) << 1) | (s & (jj - 1));
                        int ixj = i | jj;
                        int A = eq[i], Bv = eq[ixj];
                        bool desc = (i & k) != 0;
                        if ((A > Bv) != desc) { eq[i] = Bv; eq[ixj] = A; }
                    }
                    __syncthreads();
                }
        }
        __syncthreads();
        for (int i = t; i < needEq; i += 256)
            g_top[inst * CTOP + base + i] = eq[i];
    }
}

// ---------------- 5) union of pages across 4 reps + mask, deterministic -----
__global__ void union_kernel() {
    __shared__ int mask[CNPG];
    __shared__ int wtot[8];
    int bh = blockIdx.x;
    int warp = threadIdx.x >> 5, lane = threadIdx.x & 31;
    for (int i = threadIdx.x; i < CNPG; i += 256) mask[i] = 0;
    __syncthreads();
    for (int r = 0; r < CR; r++) {
        int i = threadIdx.x;
        if (i < CTOP) {
            int p = g_top[(bh * CR + r) * CTOP + i];
            atomicOr(&mask[p], 1 << r);
        }
    }
    __syncthreads();
    int base = threadIdx.x * 7;
    int cnt = 0;
    for (int j = 0; j < 7; j++) if (mask[base + j]) cnt++;
    int v = cnt;
    for (int o = 1; o < 32; o <<= 1) {
        int u = __shfl_up_sync(FULLMASK, v, o);
        if (lane >= o) v += u;
    }
    if (lane == 31) wtot[warp] = v;
    __syncthreads();
    if (threadIdx.x == 0) {
        int s = 0;
        for (int i = 0; i < 8; i++) { int t = wtot[i]; wtot[i] = s; s += t; }
        g_ucnt[bh] = (s > 1024) ? 1024 : s;
    }
    __syncthreads();
    int off = v - cnt + wtot[warp];
    for (int j = 0; j < 7; j++) {
        int p = base + j;
        int mk = mask[p];
        if (mk && off < 1024) g_uni[bh * 1024 + off++] = p | (mk << 16);
    }
}

// ---------------- write one r-state partial (contiguous-split layout) -------
__device__ __forceinline__ void wpart2(float m, float l, float4 aa, float4 ab,
                                       int b, int hr, int slot, int sub) {
    float* P = g_part + (((size_t)(b * CH + hr)) * NPART + slot) * PSTR;
    if (sub == 0) { P[0] = m; P[1] = l; }
    *(float4*)(P + 4 + sub * 4)      = aa;
    *(float4*)(P + 4 + 64 + sub * 4) = ab;
}

// ---------------- 6) prefix attention: dots-fed, V-only ----------------------
__global__ void __launch_bounds__(128, 10) prefix_kernel(const float* __restrict__ cv) {
    int bid = blockIdx.x;
    int chunk = bid % PCH;
    int bh = bid / PCH;
    int hkv = bh % CHKV, b = bh / CHKV;
    int warp = threadIdx.x >> 5, lane = threadIdx.x & 31;
    int half = lane >> 4, sub = lane & 15;
    int cnt = g_ucnt[bh];
    float m0 = -1e30f, l0 = 0.f, m1 = -1e30f, l1 = 0.f;
    float4 a0a = make_float4(0, 0, 0, 0), a0b = a0a, a1a = a0a, a1b = a0a;
    const float* dr0 = g_dots + ((size_t)bh * CR + 2 * half) * CPREF;
    const float* dr1 = dr0 + CPREF;
    int e0i = chunk * 16 + warp * 4;
    for (int ei = e0i; ei < e0i + 4 && ei < cnt; ei++) {
        int ent = g_uni[bh * 1024 + ei];
        int page = ent & 0xFFFF;
        int pm = ent >> 16;
        bool en0 = (pm >> (2 * half)) & 1;
        bool en1 = (pm >> (2 * half + 1)) & 1;
        const float* vp = cv + (((size_t)b * CSTART + (size_t)page * CPAGE) * CHKV + hkv) * CD;
#pragma unroll
        for (int g = 0; g < 2; g++) {
            float4 dA0 = *(const float4*)(dr0 + page * CPAGE + g * 8);
            float4 dA1 = *(const float4*)(dr0 + page * CPAGE + g * 8 + 4);
            float4 dB0 = *(const float4*)(dr1 + page * CPAGE + g * 8);
            float4 dB1 = *(const float4*)(dr1 + page * CPAGE + g * 8 + 4);
            float sA[8] = { dA0.x, dA0.y, dA0.z, dA0.w, dA1.x, dA1.y, dA1.z, dA1.w };
            float sB[8] = { dB0.x, dB0.y, dB0.z, dB0.w, dB1.x, dB1.y, dB1.z, dB1.w };
            float eA[8], eB[8];
            if (en0) {
                float tm = sA[0];
#pragma unroll
                for (int k = 1; k < 8; k++) tm = fmaxf(tm, sA[k]);
                float nm = fmaxf(m0, tm * CSCALE);
                float cr = __expf(m0 - nm);
                float se = 0.f;
#pragma unroll
                for (int k = 0; k < 8; k++) { eA[k] = __expf(sA[k] * CSCALE - nm); se += eA[k]; }
                l0 = l0 * cr + se; m0 = nm;
                a0a.x *= cr; a0a.y *= cr; a0a.z *= cr; a0a.w *= cr;
                a0b.x *= cr; a0b.y *= cr; a0b.z *= cr; a0b.w *= cr;
            }
            if (en1) {
                float tm = sB[0];
#pragma unroll
                for (int k = 1; k < 8; k++) tm = fmaxf(tm, sB[k]);
                float nm = fmaxf(m1, tm * CSCALE);
                float cr = __expf(m1 - nm);
                float se = 0.f;
#pragma unroll
                for (int k = 0; k < 8; k++) { eB[k] = __expf(sB[k] * CSCALE - nm); se += eB[k]; }
                l1 = l1 * cr + se; m1 = nm;
                a1a.x *= cr; a1a.y *= cr; a1a.z *= cr; a1a.w *= cr;
                a1b.x *= cr; a1b.y *= cr; a1b.z *= cr; a1b.w *= cr;
            }
#pragma unroll
            for (int k = 0; k < 8; k++) {
                const float* row = vp + (size_t)(g * 8 + k) * (CHKV * CD);
                float4 va = *(const float4*)(row + sub * 4);
                float4 vb = *(const float4*)(row + 64 + sub * 4);
                if (en0) {
                    float e = eA[k];
                    a0a.x += e * va.x; a0a.y += e * va.y; a0a.z += e * va.z; a0a.w += e * va.w;
                    a0b.x += e * vb.x; a0b.y += e * vb.y; a0b.z += e * vb.z; a0b.w += e * vb.w;
                }
                if (en1) {
                    float e = eB[k];
                    a1a.x += e * va.x; a1a.y += e * va.y; a1a.z += e * va.z; a1a.w += e * va.w;
                    a1b.x += e * vb.x; a1b.y += e * vb.y; a1b.z += e * vb.z; a1b.w += e * vb.w;
                }
            }
        }
    }
    int slot = chunk * 4 + warp;              // 0..255
    int hr = hkv * CR + 2 * half;
    wpart2(m0, l0, a0a, a0b, b, hr, slot, sub);
    wpart2(m1, l1, a1a, a1b, b, hr + 1, slot, sub);
}

// ---------------- suffix helpers (per-key flash, half-warp r-pair) -----------
#define UPD2(MM, LL, ACA, ACB, SV)                                                   \
    do {                                                                             \
        if ((SV) > (MM)) {                                                           \
            float cr_ = __expf((MM) - (SV));                                         \
            MM = (SV); LL *= cr_;                                                    \
            ACA.x *= cr_; ACA.y *= cr_; ACA.z *= cr_; ACA.w *= cr_;                  \
            ACB.x *= cr_; ACB.y *= cr_; ACB.z *= cr_; ACB.w *= cr_;                  \
        }                                                                            \
        float e_ = __expf((SV) - (MM));                                              \
        LL += e_;                                                                    \
        ACA.x += e_ * va.x; ACA.y += e_ * va.y; ACA.z += e_ * va.z; ACA.w += e_ * va.w; \
        ACB.x += e_ * vb.x; ACB.y += e_ * vb.y; ACB.z += e_ * vb.z; ACB.w += e_ * vb.w; \
    } while (0)

struct HState {
    float m0, l0, m1, l1;
    float4 a0a, a0b, a1a, a1b;
};

__device__ __forceinline__ void key_step2(HState& st, float4 ka, float4 kb,
                                          float4 va, float4 vb,
                                          float4 q0a, float4 q0b, float4 q1a, float4 q1b,
                                          bool p) {
    float v0 = dot4(ka, q0a) + dot4(kb, q0b);
    float v1 = dot4(ka, q1a) + dot4(kb, q1b);
    float a = p ? v1 : v0, bb = p ? v0 : v1;
    a += __shfl_xor_sync(FULLMASK, bb, 1);
    a += __shfl_xor_sync(FULLMASK, a, 2);
    a += __shfl_xor_sync(FULLMASK, a, 4);
    a += __shfl_xor_sync(FULLMASK, a, 8);
    a *= CSCALE;
    float so = __shfl_xor_sync(FULLMASK, a, 1);
    float sA = p ? so : a;
    float sB = p ? a : so;
    UPD2(st.m0, st.l0, st.a0a, st.a0b, sA);
    UPD2(st.m1, st.l1, st.a1a, st.a1b, sB);
}

// ---------------- 7) suffix attention (window 4096 + new token) --------------
__global__ void suffix_kernel(const float* __restrict__ ck, const float* __restrict__ cv) {
    int bid = blockIdx.x;
    int chunk = bid % SCH;
    int bh = bid / SCH;
    int hkv = bh % CHKV, b = bh / CHKV;
    int warp = threadIdx.x >> 5, lane = threadIdx.x & 31;
    int half = lane >> 4, sub = lane & 15;
    bool p = lane & 1;
    const float* qb = g_q + (b * CH + hkv * CR + 2 * half) * CD;
    float4 q0a = *(const float4*)(qb + sub * 4);
    float4 q0b = *(const float4*)(qb + 64 + sub * 4);
    float4 q1a = *(const float4*)(qb + CD + sub * 4);
    float4 q1b = *(const float4*)(qb + CD + 64 + sub * 4);
    HState st;
    st.m0 = st.m1 = -1e30f;
    st.l0 = st.l1 = 0.f;
    st.a0a = st.a0b = st.a1a = st.a1b = make_float4(0.f, 0.f, 0.f, 0.f);
    int key0 = chunk * 128 + warp * 16;
    size_t boff = (((size_t)b * CSTART + CPREF + key0) * CHKV + hkv) * CD;
    const float* kp = ck + boff;
    const float* vp = cv + boff;
    for (int g = 0; g < 8; g++) {
        const float* kr0 = kp + (size_t)(2 * g) * (CHKV * CD);
        const float* vr0 = vp + (size_t)(2 * g) * (CHKV * CD);
        const float* kr1 = kp + (size_t)(2 * g + 1) * (CHKV * CD);
        const float* vr1 = vp + (size_t)(2 * g + 1) * (CHKV * CD);
        float4 ka0 = *(const float4*)(kr0 + sub * 4), kb0 = *(const float4*)(kr0 + 64 + sub * 4);
        float4 va0 = *(const float4*)(vr0 + sub * 4), vb0 = *(const float4*)(vr0 + 64 + sub * 4);
        float4 ka1 = *(const float4*)(kr1 + sub * 4), kb1 = *(const float4*)(kr1 + 64 + sub * 4);
        float4 va1 = *(const float4*)(vr1 + sub * 4), vb1 = *(const float4*)(vr1 + 64 + sub * 4);
        key_step2(st, ka0, kb0, va0, vb0, q0a, q0b, q1a, q1b, p);
        key_step2(st, ka1, kb1, va1, vb1, q0a, q0b, q1a, q1b, p);
    }
    if (chunk == SCH - 1 && warp == 7) {       // the just-computed token
        const float* knp = g_kn + (b * CHKV + hkv) * CD;
        const float* vnp = g_vn + (b * CHKV + hkv) * CD;
        float4 ka = *(const float4*)(knp + sub * 4), kb = *(const float4*)(knp + 64 + sub * 4);
        float4 va = *(const float4*)(vnp + sub * 4), vb = *(const float4*)(vnp + 64 + sub * 4);
        key_step2(st, ka, kb, va, vb, q0a, q0b, q1a, q1b, p);
    }
    int slot = 256 + chunk * 8 + warp;
    int hr = hkv * CR + 2 * half;
    wpart2(st.m0, st.l0, st.a0a, st.a0b, b, hr, slot, sub);
    wpart2(st.m1, st.l1, st.a1a, st.a1b, b, hr + 1, slot, sub);
}

// ---------------- 8) merge all partials (exact logaddexp combine) ------------
__global__ void combine_kernel() {
    int bh = blockIdx.x;                       // b*H + h
    const float* P = g_part + (size_t)bh * NPART * PSTR;
    __shared__ float red[128];
    __shared__ float coef[NPART];
    int t = threadIdx.x;
    float mloc = -1e30f;
    for (int c = t; c < NPART; c += 128) mloc = fmaxf(mloc, P[(size_t)c * PSTR]);
    red[t] = mloc;
    for (int o = 64; o; o >>= 1) { __syncthreads(); if (t < o) red[t] = fmaxf(red[t], red[t + o]); }
    __syncthreads();
    float M = red[0];
    __syncthreads();
    float lloc = 0.f;
    for (int c = t; c < NPART; c += 128) {
        float w = __expf(P[(size_t)c * PSTR] - M);
        coef[c] = w;
        lloc += w * P[(size_t)c * PSTR + 1];
    }
    red[t] = lloc;
    for (int o = 64; o; o >>= 1) { __syncthreads(); if (t < o) red[t] += red[t + o]; }
    __syncthreads();
    float L = red[0];
    float o0 = 0.f, o1 = 0.f, o2 = 0.f, o3 = 0.f;
    for (int c = 0; c < NPART; c += 4) {       // 4 independent load chains
        o0 += coef[c]     * P[(size_t)c * PSTR + 4 + t];
        o1 += coef[c + 1] * P[(size_t)(c + 1) * PSTR + 4 + t];
        o2 += coef[c + 2] * P[(size_t)(c + 2) * PSTR + 4 + t];
        o3 += coef[c + 3] * P[(size_t)(c + 3) * PSTR + 4 + t];
    }
    float o = (o0 + o1) + (o2 + o3);
    int b = bh >> 5, h = bh & 31;
    g_attn[b * CDIM + h * CD + t] = o / L;
}

// ---------------- 9) output GEMV: 2 rows interleaved -------------------------
__global__ void out_kernel(const float* __restrict__ wo, float* __restrict__ out) {
    __shared__ float sa0[CDIM], sa1[CDIM];
    for (int i = threadIdx.x; i < CDIM; i += 256) { sa0[i] = g_attn[i]; sa1[i] = g_attn[CDIM + i]; }
    __syncthreads();
    int warp = threadIdx.x >> 5, lane = threadIdx.x & 31;
    int rowA = (blockIdx.x * 8 + warp) * 2;   // 256 blocks cover 4096 rows
    int rowB = rowA + 1;
    const float* wA = wo + (size_t)rowA * CDIM;
    const float* wB = wo + (size_t)rowB * CDIM;
    float a0 = 0.f, a1 = 0.f, b0 = 0.f, b1 = 0.f;
#pragma unroll 8
    for (int j = lane * 4; j < CDIM; j += 128) {
        float4 va = *(const float4*)(wA + j);
        float4 vb = *(const float4*)(wB + j);
        float4 x0 = *(const float4*)(sa0 + j);
        float4 x1 = *(const float4*)(sa1 + j);
        a0 += dot4(va, x0); a1 += dot4(va, x1);
        b0 += dot4(vb, x0); b1 += dot4(vb, x1);
    }
#pragma unroll
    for (int o = 16; o; o >>= 1) {
        a0 += __shfl_xor_sync(FULLMASK, a0, o);
        a1 += __shfl_xor_sync(FULLMASK, a1, o);
        b0 += __shfl_xor_sync(FULLMASK, b0, o);
        b1 += __shfl_xor_sync(FULLMASK, b1, o);
    }
    if (lane == 0) {
        out[rowA] = a0; out[CDIM + rowA] = a1;
        out[rowB] = b0; out[CDIM + rowB] = b1;
    }
}

// ---------------- streams/events for fork-join (created once, host-side) -----
struct SideStream {
    cudaStream_t s2;
    cudaEvent_t e_q, e_join;
    SideStream() {
        cudaStreamCreateWithFlags(&s2, cudaStreamNonBlocking);
        cudaEventCreateWithFlags(&e_q, cudaEventDisableTiming);
        cudaEventCreateWithFlags(&e_join, cudaEventDisableTiming);
    }
};
static SideStream g_ss;

// ---------------- launch ------------------------------------------------------
extern "C" void kernel_launch(void* const* d_in, const int* in_sizes, int n_in,
                              void* d_out, int out_size) {
    (void)in_sizes; (void)n_in; (void)out_size;
    const float* x    = (const float*)d_in[0];
    const float* fcos = (const float*)d_in[1];
    const float* fsin = (const float*)d_in[2];
    const float* ck   = (const float*)d_in[3];
    const float* cv   = (const float*)d_in[4];
    const float* wq   = (const float*)d_in[5];
    const float* wk   = (const float*)d_in[6];
    const float* wv   = (const float*)d_in[7];
    const float* wo   = (const float*)d_in[8];
    float* out = (float*)d_out;

    // q first (score's only dependency); kv on the side stream after q so it
    // overlaps with score's head instead of competing with q for bandwidth.
    qkv_q_kernel<<<256, 256>>>(x, wq, fcos, fsin);
    cudaEventRecord(g_ss.e_q, 0);

    cudaStreamWaitEvent(g_ss.s2, g_ss.e_q, 0);
    qkv_kv_kernel<<<128, 256, 0, g_ss.s2>>>(x, wk, wv, fcos, fsin);
    suffix_kernel<<<CB * CHKV * SCH, 256, 0, g_ss.s2>>>(ck, cv);
    cudaEventRecord(g_ss.e_join, g_ss.s2);

    score_kernel<<<CB * CHKV * SCHUNKS, 128>>>(ck);
    topk_kernel<<<CB * CHKV * CR, 256>>>();
    union_kernel<<<CB * CHKV, 256>>>();
    prefix_kernel<<<CB * CHKV * PCH, 128>>>(cv);

    // join before combine
    cudaStreamWaitEvent(0, g_ss.e_join, 0);
    combine_kernel<<<CB * CH, 128>>>();
    out_kernel<<<256, 256>>>(wo, out);
}